// round 2
// baseline (speedup 1.0000x reference)
#include <cuda_runtime.h>
#include <cuda_bf16.h>
#include <cstdint>

#define BMAX 8192
#define DMAX 256

#define TILE 128
#define KC   64
#define LDSA 72   // smem row stride in bf16 elems; 144B pitch -> conflict-free fragment LDS

// Scratch (allocation-free rule: __device__ globals)
__device__ __align__(16) __nv_bfloat16 g_xb[BMAX * DMAX];
__device__ float  g_sqn[BMAX];
__device__ float  g_rs[BMAX];
__device__ int    g_lab[BMAX];
__device__ int    g_is32;     // 1 = labels are int32, 0 = labels are int64
__device__ double g_acc;

// Single block: zero accumulator + detect label dtype.
// View label buffer as int32[B]. If labels are int64 (values {0,1}), every odd
// word is a zero high-half. If int32, odd words are labels (~half nonzero).
__global__ void init_kernel(const int* __restrict__ lab32, int B) {
    __shared__ int s_any;
    if (threadIdx.x == 0) { s_any = 0; g_acc = 0.0; }
    __syncthreads();
    int any = 0;
    for (int idx = 1 + 2 * threadIdx.x; idx < B; idx += 2 * blockDim.x)
        any |= lab32[idx];
    if (any) atomicOr(&s_any, 1);
    __syncthreads();
    if (threadIdx.x == 0) g_is32 = (s_any != 0) ? 1 : 0;
}

// Convert fp32 -> bf16, per-row sum and squared-norm in exact fp32, normalize label.
__global__ void prep_kernel(const float* __restrict__ x,
                            const int* __restrict__ lab32, int B, int D) {
    int row = blockIdx.x;
    int t = threadIdx.x;
    float s = 0.f, ss = 0.f;
    for (int c = t; c < D; c += blockDim.x) {
        float v = x[(size_t)row * D + c];
        g_xb[(size_t)row * D + c] = __float2bfloat16(v);
        s += v;
        ss += v * v;
    }
    #pragma unroll
    for (int o = 16; o > 0; o >>= 1) {
        s  += __shfl_down_sync(0xffffffffu, s,  o);
        ss += __shfl_down_sync(0xffffffffu, ss, o);
    }
    __shared__ float sh_s[8], sh_ss[8];
    int w = t >> 5, l = t & 31;
    if (l == 0) { sh_s[w] = s; sh_ss[w] = ss; }
    __syncthreads();
    if (t == 0) {
        float S = 0.f, SS = 0.f;
        int nw = blockDim.x >> 5;
        for (int i = 0; i < nw; i++) { S += sh_s[i]; SS += sh_ss[i]; }
        g_rs[row]  = S;
        g_sqn[row] = SS;
        // normalize label (int64 -> low word at 2*row; int32 -> word at row)
        g_lab[row] = g_is32 ? lab32[row] : lab32[2 * row];
    }
}

// Upper-triangle tiled pairwise kernel.
// CTA = 128x128 output tile, 8 warps in 2x4, warp tile = 64x32, mma m16n8k16 bf16.
__global__ __launch_bounds__(256) void pair_kernel(int B, int D, int NT) {
    __shared__ __nv_bfloat16 sA[TILE * LDSA];
    __shared__ __nv_bfloat16 sB[TILE * LDSA];
    __shared__ float red[8];

    // Map blockIdx.x -> upper-triangle tile (ti <= tj)
    int p = blockIdx.x;
    int ti = 0;
    while (p >= NT - ti) { p -= NT - ti; ti++; }
    int tj = ti + p;

    const int tid  = threadIdx.x;
    const int warp = tid >> 5;
    const int lane = tid & 31;
    const int grp  = lane >> 2;   // 0..7
    const int tg   = lane & 3;    // 0..3
    const int wm   = warp >> 2;   // 0..1  (x64 rows)
    const int wn   = warp & 3;    // 0..3  (x32 cols)

    float acc[4][4][4];
    #pragma unroll
    for (int a = 0; a < 4; a++)
        #pragma unroll
        for (int b = 0; b < 4; b++)
            #pragma unroll
            for (int c = 0; c < 4; c++) acc[a][b][c] = 0.f;

    const int r0 = ti * TILE;
    const int c0 = tj * TILE;

    for (int kc = 0; kc < D; kc += KC) {
        if (kc) __syncthreads();
        #pragma unroll
        for (int it = 0; it < 4; it++) {
            int idx = tid + 256 * it;     // 0..1023
            int row = idx >> 3;
            int c8  = idx & 7;
            uint4 va = *reinterpret_cast<const uint4*>(&g_xb[(size_t)(r0 + row) * D + kc + c8 * 8]);
            *reinterpret_cast<uint4*>(&sA[row * LDSA + c8 * 8]) = va;
            uint4 vb = *reinterpret_cast<const uint4*>(&g_xb[(size_t)(c0 + row) * D + kc + c8 * 8]);
            *reinterpret_cast<uint4*>(&sB[row * LDSA + c8 * 8]) = vb;
        }
        __syncthreads();

        #pragma unroll
        for (int ks = 0; ks < KC / 16; ks++) {
            const int k16 = ks * 16;
            uint32_t af[4][4];
            #pragma unroll
            for (int mt = 0; mt < 4; mt++) {
                int r = wm * 64 + mt * 16 + grp;
                const __nv_bfloat16* base = &sA[r * LDSA + k16 + tg * 2];
                af[mt][0] = *reinterpret_cast<const uint32_t*>(base);
                af[mt][1] = *reinterpret_cast<const uint32_t*>(base + 8 * LDSA);
                af[mt][2] = *reinterpret_cast<const uint32_t*>(base + 8);
                af[mt][3] = *reinterpret_cast<const uint32_t*>(base + 8 * LDSA + 8);
            }
            uint32_t bfm[4][2];
            #pragma unroll
            for (int nt = 0; nt < 4; nt++) {
                int c = wn * 32 + nt * 8 + grp;
                const __nv_bfloat16* base = &sB[c * LDSA + k16 + tg * 2];
                bfm[nt][0] = *reinterpret_cast<const uint32_t*>(base);
                bfm[nt][1] = *reinterpret_cast<const uint32_t*>(base + 8);
            }
            #pragma unroll
            for (int mt = 0; mt < 4; mt++)
                #pragma unroll
                for (int nt = 0; nt < 4; nt++) {
                    float* d = acc[mt][nt];
                    asm volatile(
                        "mma.sync.aligned.m16n8k16.row.col.f32.bf16.bf16.f32 "
                        "{%0,%1,%2,%3}, {%4,%5,%6,%7}, {%8,%9}, {%0,%1,%2,%3};\n"
                        : "+f"(d[0]), "+f"(d[1]), "+f"(d[2]), "+f"(d[3])
                        : "r"(af[mt][0]), "r"(af[mt][1]), "r"(af[mt][2]), "r"(af[mt][3]),
                          "r"(bfm[nt][0]), "r"(bfm[nt][1]));
                }
        }
    }

    // Epilogue: per-pair contribution.
    int iRow[8]; float sqI[8], rsI[8]; int lbI[8];
    #pragma unroll
    for (int mt = 0; mt < 4; mt++) {
        int i0 = r0 + wm * 64 + mt * 16 + grp;
        iRow[mt * 2]     = i0;
        iRow[mt * 2 + 1] = i0 + 8;
    }
    #pragma unroll
    for (int u = 0; u < 8; u++) {
        sqI[u] = g_sqn[iRow[u]];
        rsI[u] = g_rs[iRow[u]];
        lbI[u] = g_lab[iRow[u]];
    }
    int jCol[8]; float sqJ[8], rsJ[8]; int lbJ[8];
    #pragma unroll
    for (int nt = 0; nt < 4; nt++) {
        int j0 = c0 + wn * 32 + nt * 8 + tg * 2;
        jCol[nt * 2]     = j0;
        jCol[nt * 2 + 1] = j0 + 1;
    }
    #pragma unroll
    for (int u = 0; u < 8; u++) {
        sqJ[u] = g_sqn[jCol[u]];
        rsJ[u] = g_rs[jCol[u]];
        lbJ[u] = g_lab[jCol[u]];
    }

    const float D_EPS2 = (float)D * 1e-6f * 1e-6f;
    float tsum = 0.f;
    #pragma unroll
    for (int mt = 0; mt < 4; mt++)
        #pragma unroll
        for (int nt = 0; nt < 4; nt++)
            #pragma unroll
            for (int h = 0; h < 4; h++) {
                int ui = mt * 2 + (h >> 1);
                int uj = nt * 2 + (h & 1);
                int i = iRow[ui], j = jCol[uj];
                if (j > i) {
                    float gv = acc[mt][nt][h];
                    float sq = sqI[ui] + sqJ[uj] - 2.0f * gv
                             + 2e-6f * (rsI[ui] - rsJ[uj]) + D_EPS2;
                    float val;
                    if (lbI[ui] == lbJ[uj]) {
                        val = fmaxf(sq, 1e-12f);
                    } else {
                        float dd = sqrtf(fmaxf(sq, 1e-12f));
                        float tt = fmaxf(1.0f - dd, 0.0f);
                        val = tt * tt;
                    }
                    tsum += val;
                }
            }

    #pragma unroll
    for (int o = 16; o > 0; o >>= 1)
        tsum += __shfl_down_sync(0xffffffffu, tsum, o);
    if (lane == 0) red[warp] = tsum;
    __syncthreads();
    if (tid == 0) {
        float s = 0.f;
        #pragma unroll
        for (int i = 0; i < 8; i++) s += red[i];
        atomicAdd(&g_acc, (double)s);
    }
}

__global__ void fin_kernel(float* out, long long cnt) {
    out[0] = (float)(g_acc / ((double)cnt + 1e-6));
}

extern "C" void kernel_launch(void* const* d_in, const int* in_sizes, int n_in,
                              void* d_out, int out_size) {
    const float* x     = (const float*)d_in[0];
    const int*   lab32 = (const int*)d_in[1];
    int B = in_sizes[1];
    int D = in_sizes[0] / B;
    int NT = B / TILE;
    int tiles = NT * (NT + 1) / 2;
    long long cnt = (long long)B * (B - 1) / 2;

    init_kernel<<<1, 256>>>(lab32, B);
    prep_kernel<<<B, 256>>>(x, lab32, B, D);
    pair_kernel<<<tiles, 256>>>(B, D, NT);
    fin_kernel<<<1, 1>>>((float*)d_out, cnt);
}